// round 7
// baseline (speedup 1.0000x reference)
#include <cuda_runtime.h>
#include <cstdint>
#include <math.h>

#define N_ELEM 256
#define T_SEQ  32
#define H_DIM  512
#define MAXS   (N_ELEM * T_SEQ)          // worst-case executed rounds
#define NCTA_G 64                        // CTAs per layer group
#define CANARY 0x7F123456u               // NaN payload; |h|<=1 so bit-pattern unreachable

// Write-once broadcast slots for hidden vectors (one slot per executed round, per layer).
// Stored/loaded as u32 bit patterns to avoid any NaN canonicalization concerns.
__device__ unsigned g_h0[(size_t)MAXS * H_DIM];
__device__ unsigned g_h1[(size_t)MAXS * H_DIM];
__device__ unsigned g_abort;             // watchdog abort flag

__device__ __forceinline__ uint4 ldcg4u(const unsigned* p) {
    uint4 v;
    asm volatile("ld.global.cg.v4.u32 {%0,%1,%2,%3}, [%4];"
                 : "=r"(v.x), "=r"(v.y), "=r"(v.z), "=r"(v.w)
                 : "l"(p) : "memory");
    return v;
}
__device__ __forceinline__ void stcg1u(unsigned* p, unsigned v) {
    asm volatile("st.global.cg.u32 [%0], %1;" :: "l"(p), "r"(v) : "memory");
}
__device__ __forceinline__ unsigned ldcg1u(const unsigned* p) {
    unsigned v;
    asm volatile("ld.global.cg.u32 %0, [%1];" : "=r"(v) : "l"(p) : "memory");
    return v;
}
__device__ __forceinline__ bool noc(uint4 v) {   // no canary in 4 words
    return (v.x != CANARY) & (v.y != CANARY) & (v.z != CANARY) & (v.w != CANARY);
}
__device__ __forceinline__ float4 u2f(uint4 v) {
    return make_float4(__uint_as_float(v.x), __uint_as_float(v.y),
                       __uint_as_float(v.z), __uint_as_float(v.w));
}
// Warp-collective: poll one 512-float hidden vector (16 floats/lane) until no lane
// sees the canary; returns the detected data directly in registers.
__device__ __forceinline__ void poll_h(const unsigned* base, int lane, float4 v[4]) {
    const unsigned* p = base + lane * 16;
    unsigned it = 0;
    for (;;) {
        uint4 a = ldcg4u(p);
        uint4 b = ldcg4u(p + 4);
        uint4 c = ldcg4u(p + 8);
        uint4 d = ldcg4u(p + 12);
        bool ok = noc(a) & noc(b) & noc(c) & noc(d);
        if (__all_sync(0xffffffffu, (int)ok)) {
            v[0] = u2f(a); v[1] = u2f(b); v[2] = u2f(c); v[3] = u2f(d);
            return;
        }
        if ((++it & 1023u) == 0u) {
            if (ldcg1u(&g_abort) != 0u) {       // drain on watchdog abort
                v[0] = v[1] = v[2] = v[3] = make_float4(0.f, 0.f, 0.f, 0.f);
                return;
            }
            if (it >= (1u << 22)) { stcg1u(&g_abort, 1u); }
        }
    }
}
__device__ __forceinline__ float wsum(float v) {
    v += __shfl_xor_sync(0xffffffffu, v, 16);
    v += __shfl_xor_sync(0xffffffffu, v, 8);
    v += __shfl_xor_sync(0xffffffffu, v, 4);
    v += __shfl_xor_sync(0xffffffffu, v, 2);
    v += __shfl_xor_sync(0xffffffffu, v, 1);
    return v;
}
__device__ __forceinline__ float dot4(float4 a, float4 b) {
    return a.x * b.x + a.y * b.y + a.z * b.z + a.w * b.w;
}
__device__ __forceinline__ float sigmoidf_(float v) {
    return 1.0f / (1.0f + expf(-v));
}

// Canary-fill both hidden-vector slot arrays; reset abort; optionally write dates.
__global__ void init_kernel(const int* __restrict__ dates, float* __restrict__ out,
                            int write_dates) {
    size_t idx = (size_t)blockIdx.x * blockDim.x + threadIdx.x;
    size_t n4 = (size_t)MAXS * H_DIM / 4;
    uint4 cv = make_uint4(CANARY, CANARY, CANARY, CANARY);
    if (idx < n4) {
        reinterpret_cast<uint4*>(g_h0)[idx] = cv;
        reinterpret_cast<uint4*>(g_h1)[idx] = cv;
    }
    if (idx == 0) g_abort = 0u;
    if (write_dates && idx < N_ELEM) out[idx] = (float)dates[idx];
}

// Persistent 2-layer pipelined GRU, fence-free canary protocol.
// CTAs 0..63   = group A (layer 0): x-projection + recurrence, emits h0[s].
// CTAs 64..127 = group B (layer 1): consumes h0[s], own recurrence, emits h1[s]+states.
// Every warp runs fully independently: poll -> compute -> lane0 single-word publish.
__global__ void __launch_bounds__(256, 1)
gru_persistent(const int* __restrict__ dates, const float* __restrict__ x,
               const float* __restrict__ Wih0, const float* __restrict__ Whh0,
               const float* __restrict__ bih0, const float* __restrict__ bhh0,
               const float* __restrict__ Wih1, const float* __restrict__ Whh1,
               const float* __restrict__ bih1, const float* __restrict__ bhh1,
               float* __restrict__ out_states) {
    __shared__ int sdates[N_ELEM];
    int tid = threadIdx.x;
    if (tid < N_ELEM) sdates[tid] = dates[tid];
    __syncthreads();

    int warp = tid >> 5, lane = tid & 31;
    bool isB = (blockIdx.x >= NCTA_G);
    int cta  = isB ? (blockIdx.x - NCTA_G) : blockIdx.x;
    int c    = cta * 8 + warp;                    // owned output channel, 0..511

    const float* Wi = isB ? Wih1 : Wih0;
    const float* Wh = isB ? Whh1 : Whh0;
    const float* bi = isB ? bih1 : bih0;
    const float* bh = isB ? bhh1 : bhh0;

    // Register-resident weights: 3 gate rows (r,z,n) x 16 k-values for both matmuls.
    float4 wi[3][4], wh[3][4];
#pragma unroll
    for (int g = 0; g < 3; g++) {
        const float4* pi = reinterpret_cast<const float4*>(
            Wi + (size_t)(g * H_DIM + c) * H_DIM + lane * 16);
        const float4* ph = reinterpret_cast<const float4*>(
            Wh + (size_t)(g * H_DIM + c) * H_DIM + lane * 16);
#pragma unroll
        for (int j = 0; j < 4; j++) { wi[g][j] = pi[j]; wh[g][j] = ph[j]; }
    }
    float b_r  = bi[c] + bh[c];
    float b_z  = bi[H_DIM + c] + bh[H_DIM + c];
    float b_in = bi[2 * H_DIM + c];
    float b_hn = bh[2 * H_DIM + c];
    float hcur = 0.0f;

    unsigned* myH = isB ? g_h1 : g_h0;

    int s = 0;                                    // global executed-round index
    for (int n = 0; n < N_ELEM; n++) {
        bool run = (n == 0) || (sdates[n] != sdates[n - 1]);
        if (!run) {
            if (isB && lane == 0) out_states[(size_t)n * H_DIM + c] = hcur;
            continue;
        }
        for (int t = 0; t < T_SEQ; t++, s++) {
            float gr = 0.f, gz = 0.f, gn = 0.f;   // input-side partials
            float hr = 0.f, hz = 0.f, hn = 0.f;   // recurrent-side partials

            // ---- dependency-light work FIRST ----
            if (!isB) {
                // Group A: x-side projection (no cross-CTA dependency).
                float4 xv[4];
                const float4* xp = reinterpret_cast<const float4*>(
                    x + ((size_t)n * T_SEQ + t) * H_DIM + lane * 16);
#pragma unroll
                for (int j = 0; j < 4; j++) xv[j] = xp[j];
#pragma unroll
                for (int j = 0; j < 4; j++) {
                    gr += dot4(wi[0][j], xv[j]);
                    gz += dot4(wi[1][j], xv[j]);
                    gn += dot4(wi[2][j], xv[j]);
                }
            } else if (s > 0) {
                // Group B: h-side uses OWN group's previous output (already present).
                float4 hv[4];
                poll_h(g_h1 + (size_t)(s - 1) * H_DIM, lane, hv);
#pragma unroll
                for (int j = 0; j < 4; j++) {
                    hr += dot4(wh[0][j], hv[j]);
                    hz += dot4(wh[1][j], hv[j]);
                    hn += dot4(wh[2][j], hv[j]);
                }
            }

            // ---- gating dependency: poll the late-arriving vector ----
            if (!isB) {
                if (s > 0) {
                    float4 hv[4];
                    poll_h(g_h0 + (size_t)(s - 1) * H_DIM, lane, hv);
#pragma unroll
                    for (int j = 0; j < 4; j++) {
                        hr += dot4(wh[0][j], hv[j]);
                        hz += dot4(wh[1][j], hv[j]);
                        hn += dot4(wh[2][j], hv[j]);
                    }
                }
            } else {
                float4 xv[4];
                poll_h(g_h0 + (size_t)s * H_DIM, lane, xv);   // layer-0 output, round s
#pragma unroll
                for (int j = 0; j < 4; j++) {
                    gr += dot4(wi[0][j], xv[j]);
                    gz += dot4(wi[1][j], xv[j]);
                    gn += dot4(wi[2][j], xv[j]);
                }
            }

            // ---- reduce + gates + single-word weak publish ----
            float ar  = wsum(gr + hr);
            float az  = wsum(gz + hz);
            float ani = wsum(gn);
            float anh = wsum(hn);
            if (lane == 0) {
                float r  = sigmoidf_(ar + b_r);
                float z  = sigmoidf_(az + b_z);
                float nn = tanhf(ani + b_in + r * (anh + b_hn));
                hcur = (1.0f - z) * nn + z * hcur;
                stcg1u(myH + (size_t)s * H_DIM + c, __float_as_uint(hcur));
            }
        }
        if (isB && lane == 0) out_states[(size_t)n * H_DIM + c] = hcur;
    }
}

extern "C" void kernel_launch(void* const* d_in, const int* in_sizes, int n_in,
                              void* d_out, int out_size) {
    const int*   dates = (const int*)d_in[0];
    const float* x     = (const float*)d_in[1];
    const float* Wih0  = (const float*)d_in[2];
    const float* Whh0  = (const float*)d_in[3];
    const float* bih0  = (const float*)d_in[4];
    const float* bhh0  = (const float*)d_in[5];
    const float* Wih1  = (const float*)d_in[6];
    const float* Whh1  = (const float*)d_in[7];
    const float* bih1  = (const float*)d_in[8];
    const float* bhh1  = (const float*)d_in[9];
    float* out = (float*)d_out;

    // Reference returns (dates, states); if out_size includes the extra N
    // elements, dates (cast to float) come first.
    int with_dates = (out_size >= N_ELEM + N_ELEM * H_DIM) ? 1 : 0;
    float* states = out + (with_dates ? N_ELEM : 0);

    size_t n4 = (size_t)MAXS * H_DIM / 4;        // uint4 count per array
    init_kernel<<<(int)((n4 + 255) / 256), 256>>>(dates, out, with_dates);
    gru_persistent<<<128, 256>>>(dates, x, Wih0, Whh0, bih0, bhh0,
                                 Wih1, Whh1, bih1, bhh1, states);
}

// round 8
// speedup vs baseline: 7.2845x; 7.2845x over previous
#include <cuda_runtime.h>
#include <cstdint>
#include <math.h>

#define N_ELEM 256
#define T_SEQ  32
#define H_DIM  512
#define MAXS   (N_ELEM * T_SEQ)          // worst-case executed rounds
#define NCTA_G 64                        // CTAs per layer group
#define CANARY 0x7F123456u               // NaN payload; |h|<=1 so bit-pattern unreachable

// Write-once broadcast slots (u32 bit patterns; avoids NaN canonicalization concerns)
__device__ unsigned g_h0[(size_t)MAXS * H_DIM];
__device__ unsigned g_h1[(size_t)MAXS * H_DIM];
__device__ unsigned g_abort;             // watchdog abort flag

__device__ __forceinline__ uint2 ldcg2u(const unsigned* p) {
    uint2 v;
    asm volatile("ld.global.cg.v2.u32 {%0,%1}, [%2];"
                 : "=r"(v.x), "=r"(v.y) : "l"(p) : "memory");
    return v;
}
__device__ __forceinline__ void stcg1u(unsigned* p, unsigned v) {
    asm volatile("st.global.cg.u32 [%0], %1;" :: "l"(p), "r"(v) : "memory");
}
__device__ __forceinline__ unsigned ldcg1u(const unsigned* p) {
    unsigned v;
    asm volatile("ld.global.cg.u32 %0, [%1];" : "=r"(v) : "l"(p) : "memory");
    return v;
}

// Warp-collective: poll ONE disjoint 64-float slice (2 floats/lane) until no lane
// sees the canary, then deposit the slice into smem. Detect+data = one L2 RTT.
__device__ __forceinline__ void poll_slice1(const unsigned* g, float* sh, int lane) {
    const unsigned* p = g + lane * 2;
    unsigned it = 0;
    for (;;) {
        uint2 a = ldcg2u(p);
        bool ok = (a.x != CANARY) & (a.y != CANARY);
        if (__all_sync(0xffffffffu, (int)ok)) {
            sh[lane * 2]     = __uint_as_float(a.x);
            sh[lane * 2 + 1] = __uint_as_float(a.y);
            return;
        }
        if ((++it & 1023u) == 0u) {
            if (ldcg1u(&g_abort) != 0u) { sh[lane * 2] = 0.f; sh[lane * 2 + 1] = 0.f; return; }
            if (it >= (1u << 22)) stcg1u(&g_abort, 1u);
        }
    }
}
// Joint variant: poll two slices (one from each of two vectors) in one loop.
__device__ __forceinline__ void poll_slice2(const unsigned* g1, const unsigned* g2,
                                            float* sh1, float* sh2, int lane) {
    const unsigned* p1 = g1 + lane * 2;
    const unsigned* p2 = g2 + lane * 2;
    unsigned it = 0;
    for (;;) {
        uint2 a = ldcg2u(p1);
        uint2 b = ldcg2u(p2);
        bool ok = (a.x != CANARY) & (a.y != CANARY) & (b.x != CANARY) & (b.y != CANARY);
        if (__all_sync(0xffffffffu, (int)ok)) {
            sh1[lane * 2]     = __uint_as_float(a.x);
            sh1[lane * 2 + 1] = __uint_as_float(a.y);
            sh2[lane * 2]     = __uint_as_float(b.x);
            sh2[lane * 2 + 1] = __uint_as_float(b.y);
            return;
        }
        if ((++it & 1023u) == 0u) {
            if (ldcg1u(&g_abort) != 0u) {
                sh1[lane * 2] = sh1[lane * 2 + 1] = 0.f;
                sh2[lane * 2] = sh2[lane * 2 + 1] = 0.f;
                return;
            }
            if (it >= (1u << 22)) stcg1u(&g_abort, 1u);
        }
    }
}
__device__ __forceinline__ float wsum(float v) {
    v += __shfl_xor_sync(0xffffffffu, v, 16);
    v += __shfl_xor_sync(0xffffffffu, v, 8);
    v += __shfl_xor_sync(0xffffffffu, v, 4);
    v += __shfl_xor_sync(0xffffffffu, v, 2);
    v += __shfl_xor_sync(0xffffffffu, v, 1);
    return v;
}
__device__ __forceinline__ float dot4(float4 a, float4 b) {
    return a.x * b.x + a.y * b.y + a.z * b.z + a.w * b.w;
}
__device__ __forceinline__ float sigmoidf_(float v) {
    return 1.0f / (1.0f + expf(-v));
}

// Canary-fill both slot arrays; reset abort; optionally write dates (as float).
__global__ void init_kernel(const int* __restrict__ dates, float* __restrict__ out,
                            int write_dates) {
    size_t idx = (size_t)blockIdx.x * blockDim.x + threadIdx.x;
    size_t n4 = (size_t)MAXS * H_DIM / 4;
    uint4 cv = make_uint4(CANARY, CANARY, CANARY, CANARY);
    if (idx < n4) {
        reinterpret_cast<uint4*>(g_h0)[idx] = cv;
        reinterpret_cast<uint4*>(g_h1)[idx] = cv;
    }
    if (idx == 0) g_abort = 0u;
    if (write_dates && idx < N_ELEM) out[idx] = (float)dates[idx];
}

// Persistent 2-layer pipelined GRU: canary protocol with warp-sliced polling +
// smem redistribution (double-buffered; single bar per round).
// CTAs 0..63   = group A (layer 0): x-projection + recurrence, emits h0[s].
// CTAs 64..127 = group B (layer 1): consumes h0[s], own recurrence, emits h1[s]+states.
__global__ void __launch_bounds__(256, 1)
gru_persistent(const int* __restrict__ dates, const float* __restrict__ x,
               const float* __restrict__ Wih0, const float* __restrict__ Whh0,
               const float* __restrict__ bih0, const float* __restrict__ bhh0,
               const float* __restrict__ Wih1, const float* __restrict__ Whh1,
               const float* __restrict__ bih1, const float* __restrict__ bhh1,
               float* __restrict__ out_states) {
    __shared__ int sdates[N_ELEM];
    __shared__ __align__(16) float sh_prev[2][H_DIM];   // myH[s-1]
    __shared__ __align__(16) float sh_x[2][H_DIM];      // B only: h0[s]
    int tid = threadIdx.x;
    if (tid < N_ELEM) sdates[tid] = dates[tid];
    __syncthreads();

    int warp = tid >> 5, lane = tid & 31;
    bool isB = (blockIdx.x >= NCTA_G);
    int cta  = isB ? (blockIdx.x - NCTA_G) : blockIdx.x;
    int c    = cta * 8 + warp;                    // owned output channel, 0..511
    int slice = warp * 64;                        // this warp's polled slice base

    const float* Wi = isB ? Wih1 : Wih0;
    const float* Wh = isB ? Whh1 : Whh0;
    const float* bi = isB ? bih1 : bih0;
    const float* bh = isB ? bhh1 : bhh0;

    // Register-resident weights: 3 gate rows (r,z,n) x 16 k-values for both matmuls.
    float4 wi[3][4], wh[3][4];
#pragma unroll
    for (int g = 0; g < 3; g++) {
        const float4* pi = reinterpret_cast<const float4*>(
            Wi + (size_t)(g * H_DIM + c) * H_DIM + lane * 16);
        const float4* ph = reinterpret_cast<const float4*>(
            Wh + (size_t)(g * H_DIM + c) * H_DIM + lane * 16);
#pragma unroll
        for (int j = 0; j < 4; j++) { wi[g][j] = pi[j]; wh[g][j] = ph[j]; }
    }
    float b_r  = bi[c] + bh[c];
    float b_z  = bi[H_DIM + c] + bh[H_DIM + c];
    float b_in = bi[2 * H_DIM + c];
    float b_hn = bh[2 * H_DIM + c];
    float hcur = 0.0f;

    unsigned* myH = isB ? g_h1 : g_h0;

    int s = 0;                                    // global executed-round index
    for (int n = 0; n < N_ELEM; n++) {
        bool run = (n == 0) || (sdates[n] != sdates[n - 1]);
        if (!run) {
            if (isB && lane == 0) out_states[(size_t)n * H_DIM + c] = hcur;
            continue;
        }
        for (int t = 0; t < T_SEQ; t++, s++) {
            int par = s & 1;
            float gr = 0.f, gz = 0.f, gn = 0.f;

            // Group A: x-side projection first (independent of the recurrence;
            // its load latency overlaps nothing critical, but it is off the
            // detect path below).
            if (!isB) {
                float4 xv[4];
                const float4* xp = reinterpret_cast<const float4*>(
                    x + ((size_t)n * T_SEQ + t) * H_DIM + lane * 16);
#pragma unroll
                for (int j = 0; j < 4; j++) xv[j] = xp[j];
#pragma unroll
                for (int j = 0; j < 4; j++) {
                    gr += dot4(wi[0][j], xv[j]);
                    gz += dot4(wi[1][j], xv[j]);
                    gn += dot4(wi[2][j], xv[j]);
                }
            }

            // ---- sliced canary poll (detect + data in ONE L2 RTT) ----
            if (!isB) {
                if (s > 0)
                    poll_slice1(g_h0 + (size_t)(s - 1) * H_DIM + slice,
                                &sh_prev[par][slice], lane);
            } else {
                if (s > 0)
                    poll_slice2(g_h1 + (size_t)(s - 1) * H_DIM + slice,
                                g_h0 + (size_t)s * H_DIM + slice,
                                &sh_prev[par][slice], &sh_x[par][slice], lane);
                else
                    poll_slice1(g_h0 + (size_t)s * H_DIM + slice,
                                &sh_x[par][slice], lane);
            }
            __syncthreads();   // slices deposited; double-buffering makes one bar enough

            // Group B: x-side projection from h0[s] (now in smem).
            if (isB) {
                float4 xv[4];
                const float4* xp = reinterpret_cast<const float4*>(&sh_x[par][0]) + lane * 4;
#pragma unroll
                for (int j = 0; j < 4; j++) xv[j] = xp[j];
#pragma unroll
                for (int j = 0; j < 4; j++) {
                    gr += dot4(wi[0][j], xv[j]);
                    gz += dot4(wi[1][j], xv[j]);
                    gn += dot4(wi[2][j], xv[j]);
                }
            }
            // Recurrent-side projection from smem.
            float hr = 0.f, hz = 0.f, hn = 0.f;
            if (s > 0) {
                float4 hv[4];
                const float4* hp = reinterpret_cast<const float4*>(&sh_prev[par][0]) + lane * 4;
#pragma unroll
                for (int j = 0; j < 4; j++) hv[j] = hp[j];
#pragma unroll
                for (int j = 0; j < 4; j++) {
                    hr += dot4(wh[0][j], hv[j]);
                    hz += dot4(wh[1][j], hv[j]);
                    hn += dot4(wh[2][j], hv[j]);
                }
            }

            // ---- reduce + gates + single-word weak publish ----
            float ar  = wsum(gr + hr);
            float az  = wsum(gz + hz);
            float ani = wsum(gn);
            float anh = wsum(hn);
            if (lane == 0) {
                float r  = sigmoidf_(ar + b_r);
                float z  = sigmoidf_(az + b_z);
                float nn = tanhf(ani + b_in + r * (anh + b_hn));
                hcur = (1.0f - z) * nn + z * hcur;
                stcg1u(myH + (size_t)s * H_DIM + c, __float_as_uint(hcur));
            }
        }
        if (isB && lane == 0) out_states[(size_t)n * H_DIM + c] = hcur;
    }
}

extern "C" void kernel_launch(void* const* d_in, const int* in_sizes, int n_in,
                              void* d_out, int out_size) {
    const int*   dates = (const int*)d_in[0];
    const float* x     = (const float*)d_in[1];
    const float* Wih0  = (const float*)d_in[2];
    const float* Whh0  = (const float*)d_in[3];
    const float* bih0  = (const float*)d_in[4];
    const float* bhh0  = (const float*)d_in[5];
    const float* Wih1  = (const float*)d_in[6];
    const float* Whh1  = (const float*)d_in[7];
    const float* bih1  = (const float*)d_in[8];
    const float* bhh1  = (const float*)d_in[9];
    float* out = (float*)d_out;

    // Reference returns (dates, states); if out_size includes the extra N
    // elements, dates (cast to float) come first.
    int with_dates = (out_size >= N_ELEM + N_ELEM * H_DIM) ? 1 : 0;
    float* states = out + (with_dates ? N_ELEM : 0);

    size_t n4 = (size_t)MAXS * H_DIM / 4;        // uint4 count per array
    init_kernel<<<(int)((n4 + 255) / 256), 256>>>(dates, out, with_dates);
    gru_persistent<<<128, 256>>>(dates, x, Wih0, Whh0, bih0, bhh0,
                                 Wih1, Whh1, bih1, bhh1, states);
}